// round 2
// baseline (speedup 1.0000x reference)
#include <cuda_runtime.h>
#include <math.h>

// ---------------------------------------------------------------------------
// GaussianSplatRenderer3D — B=4, N=32768, H=W=512, k=11 (121 taps)
// zero (float4 grid-stride) -> splat (branchless, v4+scalar RED) -> normalize
// ---------------------------------------------------------------------------

#define KTAP 11
#define MAXPIX (4 * 512 * 512)

static __device__ float4 g_accum[MAXPIX];   // r*a, g*a, b*a, a
static __device__ float  g_accumZ[MAXPIX];  // z*a

__global__ void zero_kernel(int npix) {
    int stride = gridDim.x * blockDim.x;
    float4 z4 = make_float4(0.f, 0.f, 0.f, 0.f);
    for (int i = blockIdx.x * blockDim.x + threadIdx.x; i < npix; i += stride)
        g_accum[i] = z4;
    int nz4 = npix >> 2;
    float4* az = (float4*)g_accumZ;
    for (int i = blockIdx.x * blockDim.x + threadIdx.x; i < nz4; i += stride)
        az[i] = z4;
}

__global__ void __launch_bounds__(128)
splat_kernel(const float* __restrict__ pos, const float* __restrict__ cov,
             const float* __restrict__ rgb, const float* __restrict__ opa,
             const float* __restrict__ Km,  const float* __restrict__ Rm,
             const float* __restrict__ tv,  int B, int N, int H, int W)
{
    int gid = blockIdx.x * blockDim.x + threadIdx.x;
    if (gid >= B * N) return;
    int b = gid / N;

    const float* Kb = Km + 9 * b;
    const float* Rb = Rm + 9 * b;
    const float* tb = tv + 3 * b;

    float p0 = pos[3 * gid + 0];
    float p1 = pos[3 * gid + 1];
    float p2 = pos[3 * gid + 2];

    // Xc = R @ p + t  (mul/add chain, no FMA contraction, matches XLA dot)
    float X = __fadd_rn(__fadd_rn(__fadd_rn(__fmul_rn(Rb[0], p0), __fmul_rn(Rb[1], p1)),
                                  __fmul_rn(Rb[2], p2)), tb[0]);
    float Y = __fadd_rn(__fadd_rn(__fadd_rn(__fmul_rn(Rb[3], p0), __fmul_rn(Rb[4], p1)),
                                  __fmul_rn(Rb[5], p2)), tb[1]);
    float Z = __fadd_rn(__fadd_rn(__fadd_rn(__fmul_rn(Rb[6], p0), __fmul_rn(Rb[7], p1)),
                                  __fmul_rn(Rb[8], p2)), tb[2]);

    float zs = fmaxf(Z, 1e-6f);
    float xs = __fdiv_rn(X, zs);
    float ys = __fdiv_rn(Y, zs);

    float u = __fadd_rn(__fadd_rn(__fmul_rn(Kb[0], xs), __fmul_rn(Kb[1], ys)), Kb[2]);
    float v = __fadd_rn(__fadd_rn(__fmul_rn(Kb[3], xs), __fmul_rn(Kb[4], ys)), Kb[5]);
    float fx = Kb[0];
    float fy = Kb[4];

    float sxx = cov[3 * gid + 0];
    float syy = cov[3 * gid + 1];
    float sx = __fdiv_rn(__fmul_rn(__fsqrt_rn(fmaxf(sxx, 1e-9f)), fx), zs);
    float sy = __fdiv_rn(__fmul_rn(__fsqrt_rn(fmaxf(syy, 1e-9f)), fy), zs);

    float o  = opa[gid];
    float cr = rgb[3 * gid + 0];
    float cg = rgb[3 * gid + 1];
    float cb = rgb[3 * gid + 2];

    float isx = __fdiv_rn(1.f, fmaxf(sx, 1e-6f));
    float isy = __fdiv_rn(1.f, fmaxf(sy, 1e-6f));

    // Per-axis: clamped pixel coords + (weight * in-bounds-mask).
    // Reference scatters w*mask (exact 0 for OOB) at CLAMPED coords, so
    // always-RED with a==0 for OOB taps is bit-identical (x + 0.0f == x
    // for +0-initialized accumulators).
    float wxm[KTAP], wyo[KTAP];
    int   pxc[KTAP], pyrow[KTAP];
#pragma unroll
    for (int i = 0; i < KTAP; ++i) {
        float off = (float)(i - KTAP / 2);
        float gx = __fmul_rn(off, isx);
        float gy = __fmul_rn(off, isy);
        float ewx = __expf(-0.5f * __fmul_rn(gx, gx));
        float ewy = __expf(-0.5f * __fmul_rn(gy, gy));
        int px = __float2int_rn(__fadd_rn(u, __fmul_rn(off, sx)));
        int py = __float2int_rn(__fadd_rn(v, __fmul_rn(off, sy)));
        int pxcl = min(max(px, 0), W - 1);
        int pycl = min(max(py, 0), H - 1);
        wxm[i] = (px == pxcl) ? ewx : 0.f;
        wyo[i] = (py == pycl) ? __fmul_rn(ewy, o) : 0.f;
        pxc[i]   = pxcl;
        pyrow[i] = pycl * W;
    }

    int baseb = b * (H * W);
#pragma unroll
    for (int j = 0; j < KTAP; ++j) {
        float wj = wyo[j];
        int row = baseb + pyrow[j];
        char* base4 = (char*)g_accum  + (size_t)row * 16;
        char* basez = (char*)g_accumZ + (size_t)row * 4;
#pragma unroll
        for (int i = 0; i < KTAP; ++i) {
            float a = __fmul_rn(wxm[i], wj);
            float va0 = cr * a, va1 = cg * a, va2 = cb * a;
            float vz  = Z * a;
            char* dst4 = base4 + (size_t)(pxc[i] * 16);
            char* dstz = basez + (size_t)(pxc[i] * 4);
            asm volatile("red.global.add.v4.f32 [%0], {%1, %2, %3, %4};"
                         :: "l"(dst4), "f"(va0), "f"(va1), "f"(va2), "f"(a)
                         : "memory");
            asm volatile("red.global.add.f32 [%0], %1;"
                         :: "l"(dstz), "f"(vz)
                         : "memory");
        }
    }
}

__global__ void normalize_kernel(float* __restrict__ out, int B, int H, int W) {
    int i = blockIdx.x * blockDim.x + threadIdx.x;
    int HW = H * W;
    int npix = B * HW;
    if (i >= npix) return;
    float4 acc = g_accum[i];
    float den = fmaxf(acc.w, 1e-6f);
    int b = i / HW;
    int pix = i - b * HW;
    float* rgbout = out + (size_t)b * 3 * HW + pix;
    rgbout[0]      = __fdiv_rn(acc.x, den);
    rgbout[HW]     = __fdiv_rn(acc.y, den);
    rgbout[2 * HW] = __fdiv_rn(acc.z, den);
    out[(size_t)B * 3 * HW + (size_t)b * HW + pix] = __fdiv_rn(g_accumZ[i], den);
}

extern "C" void kernel_launch(void* const* d_in, const int* in_sizes, int n_in,
                              void* d_out, int out_size)
{
    const float* pos = (const float*)d_in[0];
    const float* cov = (const float*)d_in[1];
    const float* rgb = (const float*)d_in[2];
    const float* opa = (const float*)d_in[3];
    const float* Km  = (const float*)d_in[4];
    const float* Rm  = (const float*)d_in[5];
    const float* tv  = (const float*)d_in[6];

    int B  = in_sizes[4] / 9;
    int N  = in_sizes[0] / (3 * B);
    int HW = out_size / (4 * B);
    int W  = (int)(sqrt((double)HW) + 0.5);
    int H  = HW / W;
    int npix = B * HW;

    zero_kernel<<<592, 256>>>(npix);

    int total = B * N;
    splat_kernel<<<(total + 127) / 128, 128>>>(pos, cov, rgb, opa, Km, Rm, tv, B, N, H, W);

    normalize_kernel<<<(npix + 255) / 256, 256>>>((float*)d_out, B, H, W);
}

// round 3
// speedup vs baseline: 2.0940x; 2.0940x over previous
#include <cuda_runtime.h>
#include <cuda_fp16.h>
#include <math.h>

// ---------------------------------------------------------------------------
// GaussianSplatRenderer3D — B=4, N=32768, H=W=512, k=11 (121 taps)
// f16x2 accumulation: ONE red.global.add.noftz.v4.f16x2 per tap carries
// [r*a, g*a | b*a, a | z*a, 0 | 0, 0]  (halves the RED-lane count vs f32).
// zero -> splat (branchy tap culling) -> normalize.
// ---------------------------------------------------------------------------

#define KTAP 11
#define MAXPIX (4 * 512 * 512)

static __device__ uint4 g_acc[MAXPIX];   // 8 x f16 per pixel, 16B

__global__ void zero_kernel(int npix) {
    int stride = gridDim.x * blockDim.x;
    uint4 z = make_uint4(0u, 0u, 0u, 0u);
    for (int i = blockIdx.x * blockDim.x + threadIdx.x; i < npix; i += stride)
        g_acc[i] = z;
}

__global__ void __launch_bounds__(128)
splat_kernel(const float* __restrict__ pos, const float* __restrict__ cov,
             const float* __restrict__ rgb, const float* __restrict__ opa,
             const float* __restrict__ Km,  const float* __restrict__ Rm,
             const float* __restrict__ tv,  int B, int N, int H, int W)
{
    int gid = blockIdx.x * blockDim.x + threadIdx.x;
    if (gid >= B * N) return;
    int b = gid / N;

    const float* Kb = Km + 9 * b;
    const float* Rb = Rm + 9 * b;
    const float* tb = tv + 3 * b;

    float p0 = pos[3 * gid + 0];
    float p1 = pos[3 * gid + 1];
    float p2 = pos[3 * gid + 2];

    // Xc = R @ p + t  (mul/add chain, no FMA contraction — matches XLA dot)
    float X = __fadd_rn(__fadd_rn(__fadd_rn(__fmul_rn(Rb[0], p0), __fmul_rn(Rb[1], p1)),
                                  __fmul_rn(Rb[2], p2)), tb[0]);
    float Y = __fadd_rn(__fadd_rn(__fadd_rn(__fmul_rn(Rb[3], p0), __fmul_rn(Rb[4], p1)),
                                  __fmul_rn(Rb[5], p2)), tb[1]);
    float Z = __fadd_rn(__fadd_rn(__fadd_rn(__fmul_rn(Rb[6], p0), __fmul_rn(Rb[7], p1)),
                                  __fmul_rn(Rb[8], p2)), tb[2]);

    float zs = fmaxf(Z, 1e-6f);
    float xs = __fdiv_rn(X, zs);
    float ys = __fdiv_rn(Y, zs);

    float u = __fadd_rn(__fadd_rn(__fmul_rn(Kb[0], xs), __fmul_rn(Kb[1], ys)), Kb[2]);
    float v = __fadd_rn(__fadd_rn(__fmul_rn(Kb[3], xs), __fmul_rn(Kb[4], ys)), Kb[5]);
    float fx = Kb[0];
    float fy = Kb[4];

    float sxx = cov[3 * gid + 0];
    float syy = cov[3 * gid + 1];
    float sx = __fdiv_rn(__fmul_rn(__fsqrt_rn(fmaxf(sxx, 1e-9f)), fx), zs);
    float sy = __fdiv_rn(__fmul_rn(__fsqrt_rn(fmaxf(syy, 1e-9f)), fy), zs);

    float o  = opa[gid];
    float cr = rgb[3 * gid + 0];
    float cg = rgb[3 * gid + 1];
    float cb = rgb[3 * gid + 2];

    // Per-gaussian packed f16x2 constants for the tap inner loop
    __half2 h_rg = __floats2half2_rn(cr, cg);   // (r, g)
    __half2 h_b1 = __floats2half2_rn(cb, 1.f);  // (b, 1)
    __half2 h_z0 = __floats2half2_rn(Z,  0.f);  // (z, 0)

    float isx = __fdiv_rn(1.f, fmaxf(sx, 1e-6f));
    float isy = __fdiv_rn(1.f, fmaxf(sy, 1e-6f));

    // Per-axis weights (0 for OOB -> skipped) and precomputed byte offsets
    float wxm[KTAP], wyo[KTAP];
    int   xoff[KTAP], yrow[KTAP];
#pragma unroll
    for (int i = 0; i < KTAP; ++i) {
        float off = (float)(i - KTAP / 2);
        float gx = __fmul_rn(off, isx);
        float gy = __fmul_rn(off, isy);
        float ewx = __expf(-0.5f * __fmul_rn(gx, gx));
        float ewy = __expf(-0.5f * __fmul_rn(gy, gy));
        int px = __float2int_rn(__fadd_rn(u, __fmul_rn(off, sx)));
        int py = __float2int_rn(__fadd_rn(v, __fmul_rn(off, sy)));
        bool okx = (px >= 0) & (px < W);
        bool oky = (py >= 0) & (py < H);
        wxm[i] = okx ? ewx : 0.f;
        wyo[i] = oky ? __fmul_rn(ewy, o) : 0.f;
        xoff[i] = px * 16;                 // byte offset within row
        yrow[i] = py * W * 16;             // byte offset of row
    }

    char* baseb = (char*)g_acc + (size_t)b * (H * W) * 16;
#pragma unroll
    for (int j = 0; j < KTAP; ++j) {
        float wj = wyo[j];
        if (wj == 0.f) continue;           // OOB row (or o==0): contributes 0
        char* rowp = baseb + yrow[j];
#pragma unroll
        for (int i = 0; i < KTAP; ++i) {
            float wi = wxm[i];
            if (wi == 0.f) continue;       // OOB column: contributes 0
            float a = __fmul_rn(wi, wj);
            __half2 a2 = __floats2half2_rn(a, a);
            __half2 v0 = __hmul2(h_rg, a2);   // (r*a, g*a)
            __half2 v1 = __hmul2(h_b1, a2);   // (b*a, a)
            __half2 v2 = __hmul2(h_z0, a2);   // (z*a, 0)
            unsigned r0 = *(unsigned*)&v0;
            unsigned r1 = *(unsigned*)&v1;
            unsigned r2 = *(unsigned*)&v2;
            char* dst = rowp + xoff[i];
            asm volatile("red.global.add.noftz.v4.f16x2 [%0], {%1, %2, %3, %4};"
                         :: "l"(dst), "r"(r0), "r"(r1), "r"(r2), "r"(0u)
                         : "memory");
        }
    }
}

__global__ void normalize_kernel(float* __restrict__ out, int B, int H, int W) {
    int i = blockIdx.x * blockDim.x + threadIdx.x;
    int HW = H * W;
    int npix = B * HW;
    if (i >= npix) return;
    uint4 acc = g_acc[i];
    __half2 h0 = *(__half2*)&acc.x;   // (r*a, g*a)
    __half2 h1 = *(__half2*)&acc.y;   // (b*a, a)
    __half2 h2 = *(__half2*)&acc.z;   // (z*a, 0)
    float2 f0 = __half22float2(h0);
    float2 f1 = __half22float2(h1);
    float2 f2 = __half22float2(h2);
    float den = fmaxf(f1.y, 1e-6f);
    float inv = __fdiv_rn(1.f, den);
    int b = i / HW;
    int pix = i - b * HW;
    float* rgbout = out + (size_t)b * 3 * HW + pix;
    rgbout[0]      = f0.x * inv;
    rgbout[HW]     = f0.y * inv;
    rgbout[2 * HW] = f1.x * inv;
    out[(size_t)B * 3 * HW + (size_t)b * HW + pix] = f2.x * inv;
}

extern "C" void kernel_launch(void* const* d_in, const int* in_sizes, int n_in,
                              void* d_out, int out_size)
{
    const float* pos = (const float*)d_in[0];
    const float* cov = (const float*)d_in[1];
    const float* rgb = (const float*)d_in[2];
    const float* opa = (const float*)d_in[3];
    const float* Km  = (const float*)d_in[4];
    const float* Rm  = (const float*)d_in[5];
    const float* tv  = (const float*)d_in[6];

    int B  = in_sizes[4] / 9;
    int N  = in_sizes[0] / (3 * B);
    int HW = out_size / (4 * B);
    int W  = (int)(sqrt((double)HW) + 0.5);
    int H  = HW / W;
    int npix = B * HW;

    zero_kernel<<<592, 256>>>(npix);

    int total = B * N;
    splat_kernel<<<(total + 127) / 128, 128>>>(pos, cov, rgb, opa, Km, Rm, tv, B, N, H, W);

    normalize_kernel<<<(npix + 255) / 256, 256>>>((float*)d_out, B, H, W);
}